// round 14
// baseline (speedup 1.0000x reference)
#include <cuda_runtime.h>
#include <cuda_fp16.h>
#include <math_constants.h>
#include <cstdint>

#define T 2048
#define D 1024
#define H 16
#define HD 64
#define BH 32
#define MTOT 4096
#define GKP 72     // gemm smem k-stride (64 elems + 8 pad)
#define FP 72      // flash smem row stride (64 elems + 8 pad)
#define TP 136     // V-transpose smem row stride (128 + 8)

// ---------------- scratch (allocation-free device globals) ----------------
__device__ __half g_xh[(size_t)MTOT * D];
__device__ __half g_Wh[4][(size_t)D * D];
__device__ __half g_Q[(size_t)BH * T * HD];                   // fp16, pre-scaled by log2e/8
__device__ __half g_K[(size_t)BH * T * HD];                   // fp16
__device__ __half g_Vt[(size_t)BH * HD * T];                  // fp16, transposed [bh][c][t]
__device__ __half g_C[(size_t)MTOT * D];                      // ctx, fp16

// ---------------- PTX helpers ----------------
__device__ __forceinline__ unsigned su32(const void* p) {
    return (unsigned)__cvta_generic_to_shared(p);
}
__device__ __forceinline__ void ldm4(unsigned* r, const void* p) {
    unsigned a = su32(p);
    asm volatile("ldmatrix.sync.aligned.m8n8.x4.shared.b16 {%0,%1,%2,%3},[%4];"
                 : "=r"(r[0]), "=r"(r[1]), "=r"(r[2]), "=r"(r[3]) : "r"(a));
}
__device__ __forceinline__ void mma16816(float* c, const unsigned* a,
                                         unsigned b0, unsigned b1) {
    asm volatile("mma.sync.aligned.m16n8k16.row.col.f32.f16.f16.f32 "
                 "{%0,%1,%2,%3},{%4,%5,%6,%7},{%8,%9},{%0,%1,%2,%3};"
                 : "+f"(c[0]), "+f"(c[1]), "+f"(c[2]), "+f"(c[3])
                 : "r"(a[0]), "r"(a[1]), "r"(a[2]), "r"(a[3]), "r"(b0), "r"(b1));
}
__device__ __forceinline__ void cp16(void* s, const void* g) {
    asm volatile("cp.async.cg.shared.global [%0],[%1],16;" :: "r"(su32(s)), "l"(g));
}
#define CPCOMMIT asm volatile("cp.async.commit_group;")
template <int N> __device__ __forceinline__ void cpwait() {
    asm volatile("cp.async.wait_group %0;" :: "n"(N));
}

__device__ __forceinline__ unsigned pack2h(float v0, float v1) {
    return ((unsigned)__half_as_ushort(__float2half_rn(v1)) << 16)
         | __half_as_ushort(__float2half_rn(v0));
}

// ---------------- 64-wide tile stage ----------------
template <int ROWS>
__device__ __forceinline__ void stage64(__half* sm, const __half* g,
                                        long ld, int k0, int tid) {
    #pragma unroll
    for (int id = tid; id < ROWS * 8; id += 256) {
        int row = id >> 3;
        int cc  = (id & 7) * 8;
        cp16(sm + row * GKP + cc, g + (size_t)row * ld + k0 + cc);
    }
}

// ---------------- fp16 1-term NT GEMM, BK=64, 3-stage, 1 barrier/iter ----------------
template <int MI, int NI, int BN>
__device__ __forceinline__ void gemm1(
    float* cf,
    const __half* __restrict__ gA, long lda,
    const __half* __restrict__ gB, long ldb,
    int K)
{
    extern __shared__ char smraw[];
    __half* sm = (__half*)smraw;
    constexpr int S   = 3;
    constexpr int ASZ = 128 * GKP;
    constexpr int BSZ = BN * GKP;
    __half* A0 = sm;
    __half* B0 = A0 + S * ASZ;

    const int tid  = threadIdx.x;
    const int w    = tid >> 5;
    const int lane = tid & 31;
    const int NWN  = BN / (NI * 8);
    const int warp_m = (w / NWN) * (MI * 16);
    const int warp_n = (w % NWN) * (NI * 8);

    const int ar = warp_m + (lane & 15);
    const int ac = (lane >> 4) << 3;
    const int brow = warp_n + (lane & 15);
    const int bcol = (lane >> 4) << 3;

    const int nit = K >> 6;

    #pragma unroll
    for (int s = 0; s < S - 1; ++s) {
        stage64<128>(A0 + s * ASZ, gA, lda, s << 6, tid);
        stage64<BN >(B0 + s * BSZ, gB, ldb, s << 6, tid);
        CPCOMMIT;
    }

    for (int it = 0; it < nit; ++it) {
        cpwait<S - 2>();
        __syncthreads();

        if (it + S - 1 < nit) {
            int nb = (it + S - 1) % S;
            int k0 = (it + S - 1) << 6;
            stage64<128>(A0 + nb * ASZ, gA, lda, k0, tid);
            stage64<BN >(B0 + nb * BSZ, gB, ldb, k0, tid);
        }
        CPCOMMIT;

        const __half* sA = A0 + (it % S) * ASZ;
        const __half* sB = B0 + (it % S) * BSZ;

        #pragma unroll
        for (int ks = 0; ks < 64; ks += 16) {
            unsigned ah[MI][4];
            #pragma unroll
            for (int mi = 0; mi < MI; mi++)
                ldm4(ah[mi], sA + (ar + mi * 16) * GKP + ks + ac);
            #pragma unroll
            for (int ni2 = 0; ni2 < NI / 2; ni2++) {
                unsigned b4[4];
                ldm4(b4, sB + (brow + ni2 * 16) * GKP + ks + bcol);
                #pragma unroll
                for (int half = 0; half < 2; half++) {
                    int ni = ni2 * 2 + half;
                    #pragma unroll
                    for (int mi = 0; mi < MI; mi++)
                        mma16816(cf + (mi * NI + ni) * 4, ah[mi], b4[half], b4[half + 2]);
                }
            }
        }
    }
    cpwait<0>();
}

// ---------------- fused conversion kernel (hi planes only) ----------------
__global__ __launch_bounds__(256) void conv_all(
    const float* __restrict__ x,  const float* __restrict__ Wq,
    const float* __restrict__ Wk, const float* __restrict__ Wv,
    const float* __restrict__ Wo)
{
    const int blk = blockIdx.x;
    const float* src;
    unsigned* dh;
    int i;
    if (blk < 4096) {
        src = x; dh = (unsigned*)g_xh;
        i = blk * 256 + threadIdx.x;
    } else {
        int wb = blk - 4096;
        int wi = wb >> 10;
        src = (wi == 0) ? Wq : (wi == 1) ? Wk : (wi == 2) ? Wv : Wo;
        dh = (unsigned*)g_Wh[wi];
        i = (wb & 1023) * 256 + threadIdx.x;
    }
    float4 v = ((const float4*)src)[i];
    dh[2 * i]     = pack2h(v.x, v.y);
    dh[2 * i + 1] = pack2h(v.z, v.w);
}

// ---------------- GEMM 1: QKV projection (1-term) ----------------
__global__ __launch_bounds__(256, 2) void qkv_mma() {
    const int z  = blockIdx.z;
    const int m0 = blockIdx.y * 128;
    const int n0 = blockIdx.x * 128;

    float cf[64];
    #pragma unroll
    for (int i = 0; i < 64; i++) cf[i] = 0.0f;

    gemm1<4, 4, 128>(cf,
        g_xh + (size_t)m0 * D, D,
        g_Wh[z] + (size_t)n0 * D, D, D);

    const int tid = threadIdx.x;
    const int w = tid >> 5, lane = tid & 31;
    const int warp_m = (w >> 2) * 64, warp_n = (w & 3) * 32;
    const float QSCALE = 0.125f * 1.4426950408889634f;

    if (z < 2) {
        #pragma unroll
        for (int mi = 0; mi < 4; mi++)
            #pragma unroll
            for (int ni = 0; ni < 4; ni++)
                #pragma unroll
                for (int hf = 0; hf < 2; hf++) {
                    float v0 = cf[(mi * 4 + ni) * 4 + hf * 2 + 0];
                    float v1 = cf[(mi * 4 + ni) * 4 + hf * 2 + 1];
                    int gm = m0 + warp_m + mi * 16 + (lane >> 2) + hf * 8;
                    int gn = n0 + warp_n + ni * 8 + (lane & 3) * 2;
                    int b = gm >> 11, t = gm & (T - 1);
                    int h = gn >> 6,  c = gn & (HD - 1);
                    size_t o = ((size_t)(b * H + h) * T + t) * HD + c;
                    if (z == 0)
                        *(unsigned*)(g_Q + o) = pack2h(v0 * QSCALE, v1 * QSCALE);
                    else
                        *(unsigned*)(g_K + o) = pack2h(v0, v1);
                }
    } else {
        extern __shared__ char smraw[];
        __half* smT = (__half*)smraw;
        __syncthreads();

        #pragma unroll
        for (int mi = 0; mi < 4; mi++)
            #pragma unroll
            for (int ni = 0; ni < 4; ni++)
                #pragma unroll
                for (int hf = 0; hf < 2; hf++) {
                    float v0 = cf[(mi * 4 + ni) * 4 + hf * 2 + 0];
                    float v1 = cf[(mi * 4 + ni) * 4 + hf * 2 + 1];
                    int ml = warp_m + mi * 16 + (lane >> 2) + hf * 8;
                    int nl = warp_n + ni * 8 + (lane & 3) * 2;
                    smT[nl * TP + ml]       = __float2half_rn(v0);
                    smT[(nl + 1) * TP + ml] = __float2half_rn(v1);
                }
        __syncthreads();

        const int b  = m0 >> 11;
        const int t0 = (m0 & (T - 1)) + (tid & 1) * 64;
        const int nl = tid >> 1;
        const int gn = n0 + nl;
        const int h  = gn >> 6, c = gn & (HD - 1);
        const uint4* srcv = (const uint4*)(smT + nl * TP + (tid & 1) * 64);
        uint4* dstv = (uint4*)(g_Vt + ((size_t)(b * H + h) * HD + c) * T + t0);
        #pragma unroll
        for (int q = 0; q < 8; ++q) dstv[q] = srcv[q];
    }
}

// ---------------- Flash attention: 3 CTAs/SM, exp/PV interleaved ----------------
__global__ __launch_bounds__(256, 3) void flash2() {
    const int bh = blockIdx.y;
    const int m0 = blockIdx.x * 128;
    const size_t qb = (size_t)bh * T * HD;
    const size_t vb = (size_t)bh * HD * T;

    extern __shared__ char smraw[];
    __half* sQ = (__half*)smraw;            // 128*FP
    __half* sK = sQ + 128 * FP;             // 3 x 64*FP
    __half* sV = sK + 3 * 64 * FP;          // 3 x 64*FP

    const int tid = threadIdx.x, w = tid >> 5, lane = tid & 31;

    const int ar   = w * 16 + (lane & 15);
    const int ac   = (lane >> 4) << 3;
    const int brow = lane & 15;
    const int bcol = (lane >> 4) << 3;

    auto stageKV = [&](int buf, int kt) {
        const size_t koff = qb + (size_t)kt * 64 * HD;
        const size_t voff = vb + (size_t)kt * 64;
        #pragma unroll 2
        for (int id = tid; id < 512; id += 256) {
            int r = id >> 3, c8 = (id & 7) << 3;
            cp16(sK + buf * 64 * FP + r * FP + c8, g_K  + koff + (size_t)r * HD + c8);
            cp16(sV + buf * 64 * FP + r * FP + c8, g_Vt + voff + (size_t)r * T + c8);
        }
    };

    #pragma unroll 2
    for (int id = tid; id < 1024; id += 256) {
        int r = id >> 3, c8 = (id & 7) << 3;
        cp16(sQ + r * FP + c8, g_Q + qb + (size_t)(m0 + r) * HD + c8);
    }
    stageKV(0, 0);
    CPCOMMIT;
    stageKV(1, 1);
    CPCOMMIT;

    float o[8][4];
    #pragma unroll
    for (int i = 0; i < 8; i++)
        #pragma unroll
        for (int j = 0; j < 4; j++) o[i][j] = 0.0f;
    float lsum0 = 0.0f, lsum1 = 0.0f;

    #pragma unroll 1
    for (int kt = 0; kt < 32; ++kt) {
        cpwait<1>();
        __syncthreads();

        if (kt + 2 < 32) stageKV((kt + 2) % 3, kt + 2);
        CPCOMMIT;

        const __half* K_ = sK + (kt % 3) * 64 * FP;
        const __half* V_ = sV + (kt % 3) * 64 * FP;

        float S[8][4];
        #pragma unroll
        for (int i = 0; i < 8; i++)
            #pragma unroll
            for (int j = 0; j < 4; j++) S[i][j] = 0.0f;

        #pragma unroll
        for (int ks = 0; ks < 64; ks += 16) {
            unsigned ah[4];
            ldm4(ah, sQ + ar * FP + ks + ac);
            #pragma unroll
            for (int nt2 = 0; nt2 < 4; ++nt2) {
                unsigned b4[4];
                ldm4(b4, K_ + (nt2 * 16 + brow) * FP + ks + bcol);
                mma16816(S[nt2 * 2],     ah, b4[0], b4[2]);
                mma16816(S[nt2 * 2 + 1], ah, b4[1], b4[3]);
            }
        }

        // ---- exp2 interleaved with PV: MUFU of group j+1 overlaps HMMA of group j ----
        #pragma unroll
        for (int j = 0; j < 4; ++j) {
            float e0 = exp2f(S[2*j  ][0]), e1 = exp2f(S[2*j  ][1]);
            float e2 = exp2f(S[2*j  ][2]), e3 = exp2f(S[2*j  ][3]);
            float e4 = exp2f(S[2*j+1][0]), e5 = exp2f(S[2*j+1][1]);
            float e6 = exp2f(S[2*j+1][2]), e7 = exp2f(S[2*j+1][3]);
            lsum0 += e0 + e1 + e4 + e5;
            lsum1 += e2 + e3 + e6 + e7;
            unsigned ph[4];
            ph[0] = pack2h(e0, e1);
            ph[1] = pack2h(e2, e3);
            ph[2] = pack2h(e4, e5);
            ph[3] = pack2h(e6, e7);
            #pragma unroll
            for (int nt2 = 0; nt2 < 4; ++nt2) {
                unsigned v4[4];
                ldm4(v4, V_ + (nt2 * 16 + brow) * FP + j * 16 + bcol);
                mma16816(o[nt2 * 2],     ph, v4[0], v4[2]);
                mma16816(o[nt2 * 2 + 1], ph, v4[1], v4[3]);
            }
        }
    }

    #pragma unroll
    for (int ofs = 1; ofs <= 2; ofs <<= 1) {
        lsum0 += __shfl_xor_sync(0xFFFFFFFFu, lsum0, ofs);
        lsum1 += __shfl_xor_sync(0xFFFFFFFFu, lsum1, ofs);
    }
    const float inv0 = 1.0f / lsum0;
    const float inv1 = 1.0f / lsum1;

    const int b = bh >> 4, h = bh & 15;
    const int gr = lane >> 2, gc2 = (lane & 3) * 2;

    #pragma unroll
    for (int nt = 0; nt < 8; ++nt) {
        #pragma unroll
        for (int hf = 0; hf < 2; ++hf) {
            float v0 = o[nt][hf * 2 + 0] * (hf ? inv1 : inv0);
            float v1 = o[nt][hf * 2 + 1] * (hf ? inv1 : inv0);
            int gm = m0 + w * 16 + gr + hf * 8;
            int gn = h * HD + nt * 8 + gc2;
            size_t off = ((size_t)(b * T + gm)) * D + gn;
            *(unsigned*)(g_C + off) = pack2h(v0, v1);
        }
    }
}

// ---------------- GEMM 4: out = ctx @ Wo^T + bo (1-term) ----------------
__global__ __launch_bounds__(256, 2) void out_mma(const float* __restrict__ bo,
                                                  float* __restrict__ out) {
    const int m0 = blockIdx.y * 128;
    const int n0 = blockIdx.x * 128;

    float cf[64];
    #pragma unroll
    for (int i = 0; i < 64; i++) cf[i] = 0.0f;

    gemm1<4, 4, 128>(cf,
        g_C + (size_t)m0 * D, D,
        g_Wh[3] + (size_t)n0 * D, D, D);

    const int w = threadIdx.x >> 5, lane = threadIdx.x & 31;
    const int warp_m = (w >> 2) * 64, warp_n = (w & 3) * 32;

    #pragma unroll
    for (int mi = 0; mi < 4; mi++)
        #pragma unroll
        for (int ni = 0; ni < 4; ni++)
            #pragma unroll
            for (int hf = 0; hf < 2; hf++) {
                float v0 = cf[(mi * 4 + ni) * 4 + hf * 2 + 0];
                float v1 = cf[(mi * 4 + ni) * 4 + hf * 2 + 1];
                int gm = m0 + warp_m + mi * 16 + (lane >> 2) + hf * 8;
                int gn = n0 + warp_n + ni * 8 + (lane & 3) * 2;
                v0 += bo[gn];
                v1 += bo[gn + 1];
                *(float2*)(out + (size_t)gm * D + gn) = make_float2(v0, v1);
            }
}

// ---------------- launch ----------------
extern "C" void kernel_launch(void* const* d_in, const int* in_sizes, int n_in,
                              void* d_out, int out_size)
{
    const float* x  = (const float*)d_in[0];
    const float* Wq = (const float*)d_in[1];
    const float* Wk = (const float*)d_in[2];
    const float* Wv = (const float*)d_in[3];
    const float* Wo = (const float*)d_in[4];
    const float* bo = (const float*)d_in[5];
    float* out = (float*)d_out;

    const int SM_G1    = 6 * 128 * GKP * 2;            // 110592 B
    const int SM_FLASH = (128 * FP + 6 * 64 * FP) * 2; // 73728 B
    cudaFuncSetAttribute(qkv_mma, cudaFuncAttributeMaxDynamicSharedMemorySize, SM_G1);
    cudaFuncSetAttribute(flash2,  cudaFuncAttributeMaxDynamicSharedMemorySize, SM_FLASH);
    cudaFuncSetAttribute(out_mma, cudaFuncAttributeMaxDynamicSharedMemorySize, SM_G1);

    conv_all<<<8192, 256>>>(x, Wq, Wk, Wv, Wo);
    qkv_mma<<<dim3(8, 32, 3), 256, SM_G1>>>();
    flash2 <<<dim3(16, 32),   256, SM_FLASH>>>();
    out_mma<<<dim3(8, 32),    256, SM_G1>>>(bo, out);
}

// round 15
// speedup vs baseline: 1.0343x; 1.0343x over previous
#include <cuda_runtime.h>
#include <cuda_fp16.h>
#include <math_constants.h>
#include <cstdint>

#define T 2048
#define D 1024
#define H 16
#define HD 64
#define BH 32
#define MTOT 4096
#define GKP 72     // gemm smem k-stride (64 elems + 8 pad)
#define FP 72      // flash smem row stride (64 elems + 8 pad)
#define TP 136     // V-transpose smem row stride (128 + 8)

// ---------------- scratch (allocation-free device globals) ----------------
__device__ __half g_xh[(size_t)MTOT * D];
__device__ __half g_Wh[4][(size_t)D * D];
__device__ __half g_Q[(size_t)BH * T * HD];                   // fp16, pre-scaled by log2e/8
__device__ __half g_K[(size_t)BH * T * HD];                   // fp16
__device__ __half g_Vt[(size_t)BH * HD * T];                  // fp16, transposed [bh][c][t]
__device__ __half g_C[(size_t)MTOT * D];                      // ctx, fp16

// ---------------- PTX helpers ----------------
__device__ __forceinline__ unsigned su32(const void* p) {
    return (unsigned)__cvta_generic_to_shared(p);
}
__device__ __forceinline__ void ldm4(unsigned* r, const void* p) {
    unsigned a = su32(p);
    asm volatile("ldmatrix.sync.aligned.m8n8.x4.shared.b16 {%0,%1,%2,%3},[%4];"
                 : "=r"(r[0]), "=r"(r[1]), "=r"(r[2]), "=r"(r[3]) : "r"(a));
}
__device__ __forceinline__ void mma16816(float* c, const unsigned* a,
                                         unsigned b0, unsigned b1) {
    asm volatile("mma.sync.aligned.m16n8k16.row.col.f32.f16.f16.f32 "
                 "{%0,%1,%2,%3},{%4,%5,%6,%7},{%8,%9},{%0,%1,%2,%3};"
                 : "+f"(c[0]), "+f"(c[1]), "+f"(c[2]), "+f"(c[3])
                 : "r"(a[0]), "r"(a[1]), "r"(a[2]), "r"(a[3]), "r"(b0), "r"(b1));
}
__device__ __forceinline__ void cp16(void* s, const void* g) {
    asm volatile("cp.async.cg.shared.global [%0],[%1],16;" :: "r"(su32(s)), "l"(g));
}
#define CPCOMMIT asm volatile("cp.async.commit_group;")
template <int N> __device__ __forceinline__ void cpwait() {
    asm volatile("cp.async.wait_group %0;" :: "n"(N));
}

__device__ __forceinline__ unsigned pack2h(float v0, float v1) {
    return ((unsigned)__half_as_ushort(__float2half_rn(v1)) << 16)
         | __half_as_ushort(__float2half_rn(v0));
}

// ---------------- 64-wide tile stage ----------------
template <int ROWS>
__device__ __forceinline__ void stage64(__half* sm, const __half* g,
                                        long ld, int k0, int tid) {
    #pragma unroll
    for (int id = tid; id < ROWS * 8; id += 256) {
        int row = id >> 3;
        int cc  = (id & 7) * 8;
        cp16(sm + row * GKP + cc, g + (size_t)row * ld + k0 + cc);
    }
}

// ---------------- fp16 1-term NT GEMM, BK=64, 3-stage, 1 barrier/iter ----------------
template <int MI, int NI, int BN>
__device__ __forceinline__ void gemm1(
    float* cf,
    const __half* __restrict__ gA, long lda,
    const __half* __restrict__ gB, long ldb,
    int K)
{
    extern __shared__ char smraw[];
    __half* sm = (__half*)smraw;
    constexpr int S   = 3;
    constexpr int ASZ = 128 * GKP;
    constexpr int BSZ = BN * GKP;
    __half* A0 = sm;
    __half* B0 = A0 + S * ASZ;

    const int tid  = threadIdx.x;
    const int w    = tid >> 5;
    const int lane = tid & 31;
    const int NWN  = BN / (NI * 8);
    const int warp_m = (w / NWN) * (MI * 16);
    const int warp_n = (w % NWN) * (NI * 8);

    const int ar = warp_m + (lane & 15);
    const int ac = (lane >> 4) << 3;
    const int brow = warp_n + (lane & 15);
    const int bcol = (lane >> 4) << 3;

    const int nit = K >> 6;

    #pragma unroll
    for (int s = 0; s < S - 1; ++s) {
        stage64<128>(A0 + s * ASZ, gA, lda, s << 6, tid);
        stage64<BN >(B0 + s * BSZ, gB, ldb, s << 6, tid);
        CPCOMMIT;
    }

    for (int it = 0; it < nit; ++it) {
        cpwait<S - 2>();
        __syncthreads();

        if (it + S - 1 < nit) {
            int nb = (it + S - 1) % S;
            int k0 = (it + S - 1) << 6;
            stage64<128>(A0 + nb * ASZ, gA, lda, k0, tid);
            stage64<BN >(B0 + nb * BSZ, gB, ldb, k0, tid);
        }
        CPCOMMIT;

        const __half* sA = A0 + (it % S) * ASZ;
        const __half* sB = B0 + (it % S) * BSZ;

        #pragma unroll
        for (int ks = 0; ks < 64; ks += 16) {
            unsigned ah[MI][4];
            #pragma unroll
            for (int mi = 0; mi < MI; mi++)
                ldm4(ah[mi], sA + (ar + mi * 16) * GKP + ks + ac);
            #pragma unroll
            for (int ni2 = 0; ni2 < NI / 2; ni2++) {
                unsigned b4[4];
                ldm4(b4, sB + (brow + ni2 * 16) * GKP + ks + bcol);
                #pragma unroll
                for (int half = 0; half < 2; half++) {
                    int ni = ni2 * 2 + half;
                    #pragma unroll
                    for (int mi = 0; mi < MI; mi++)
                        mma16816(cf + (mi * NI + ni) * 4, ah[mi], b4[half], b4[half + 2]);
                }
            }
        }
    }
    cpwait<0>();
}

// ---------------- fused conversion kernel (hi planes only) ----------------
__global__ __launch_bounds__(256) void conv_all(
    const float* __restrict__ x,  const float* __restrict__ Wq,
    const float* __restrict__ Wk, const float* __restrict__ Wv,
    const float* __restrict__ Wo)
{
    const int blk = blockIdx.x;
    const float* src;
    unsigned* dh;
    int i;
    if (blk < 4096) {
        src = x; dh = (unsigned*)g_xh;
        i = blk * 256 + threadIdx.x;
    } else {
        int wb = blk - 4096;
        int wi = wb >> 10;
        src = (wi == 0) ? Wq : (wi == 1) ? Wk : (wi == 2) ? Wv : Wo;
        dh = (unsigned*)g_Wh[wi];
        i = (wb & 1023) * 256 + threadIdx.x;
    }
    float4 v = ((const float4*)src)[i];
    dh[2 * i]     = pack2h(v.x, v.y);
    dh[2 * i + 1] = pack2h(v.z, v.w);
}

// ---------------- GEMM 1: QKV projection (1-term) ----------------
__global__ __launch_bounds__(256, 2) void qkv_mma() {
    const int z  = blockIdx.z;
    const int m0 = blockIdx.y * 128;
    const int n0 = blockIdx.x * 128;

    float cf[64];
    #pragma unroll
    for (int i = 0; i < 64; i++) cf[i] = 0.0f;

    gemm1<4, 4, 128>(cf,
        g_xh + (size_t)m0 * D, D,
        g_Wh[z] + (size_t)n0 * D, D, D);

    const int tid = threadIdx.x;
    const int w = tid >> 5, lane = tid & 31;
    const int warp_m = (w >> 2) * 64, warp_n = (w & 3) * 32;
    const float QSCALE = 0.125f * 1.4426950408889634f;

    if (z < 2) {
        #pragma unroll
        for (int mi = 0; mi < 4; mi++)
            #pragma unroll
            for (int ni = 0; ni < 4; ni++)
                #pragma unroll
                for (int hf = 0; hf < 2; hf++) {
                    float v0 = cf[(mi * 4 + ni) * 4 + hf * 2 + 0];
                    float v1 = cf[(mi * 4 + ni) * 4 + hf * 2 + 1];
                    int gm = m0 + warp_m + mi * 16 + (lane >> 2) + hf * 8;
                    int gn = n0 + warp_n + ni * 8 + (lane & 3) * 2;
                    int b = gm >> 11, t = gm & (T - 1);
                    int h = gn >> 6,  c = gn & (HD - 1);
                    size_t o = ((size_t)(b * H + h) * T + t) * HD + c;
                    if (z == 0)
                        *(unsigned*)(g_Q + o) = pack2h(v0 * QSCALE, v1 * QSCALE);
                    else
                        *(unsigned*)(g_K + o) = pack2h(v0, v1);
                }
    } else {
        extern __shared__ char smraw[];
        __half* smT = (__half*)smraw;
        __syncthreads();

        #pragma unroll
        for (int mi = 0; mi < 4; mi++)
            #pragma unroll
            for (int ni = 0; ni < 4; ni++)
                #pragma unroll
                for (int hf = 0; hf < 2; hf++) {
                    float v0 = cf[(mi * 4 + ni) * 4 + hf * 2 + 0];
                    float v1 = cf[(mi * 4 + ni) * 4 + hf * 2 + 1];
                    int ml = warp_m + mi * 16 + (lane >> 2) + hf * 8;
                    int nl = warp_n + ni * 8 + (lane & 3) * 2;
                    smT[nl * TP + ml]       = __float2half_rn(v0);
                    smT[(nl + 1) * TP + ml] = __float2half_rn(v1);
                }
        __syncthreads();

        const int b  = m0 >> 11;
        const int t0 = (m0 & (T - 1)) + (tid & 1) * 64;
        const int nl = tid >> 1;
        const int gn = n0 + nl;
        const int h  = gn >> 6, c = gn & (HD - 1);
        const uint4* srcv = (const uint4*)(smT + nl * TP + (tid & 1) * 64);
        uint4* dstv = (uint4*)(g_Vt + ((size_t)(b * H + h) * HD + c) * T + t0);
        #pragma unroll
        for (int q = 0; q < 8; ++q) dstv[q] = srcv[q];
    }
}

// ---------------- Flash attention: 2 CTAs/SM (R13), exp/PV interleaved ----------------
__global__ __launch_bounds__(256, 2) void flash2() {
    const int bh = blockIdx.y;
    const int m0 = blockIdx.x * 128;
    const size_t qb = (size_t)bh * T * HD;
    const size_t vb = (size_t)bh * HD * T;

    extern __shared__ char smraw[];
    __half* sQ = (__half*)smraw;            // 128*FP
    __half* sK = sQ + 128 * FP;             // 3 x 64*FP
    __half* sV = sK + 3 * 64 * FP;          // 3 x 64*FP

    const int tid = threadIdx.x, w = tid >> 5, lane = tid & 31;

    const int ar   = w * 16 + (lane & 15);
    const int ac   = (lane >> 4) << 3;
    const int brow = lane & 15;
    const int bcol = (lane >> 4) << 3;

    auto stageKV = [&](int buf, int kt) {
        const size_t koff = qb + (size_t)kt * 64 * HD;
        const size_t voff = vb + (size_t)kt * 64;
        #pragma unroll 2
        for (int id = tid; id < 512; id += 256) {
            int r = id >> 3, c8 = (id & 7) << 3;
            cp16(sK + buf * 64 * FP + r * FP + c8, g_K  + koff + (size_t)r * HD + c8);
            cp16(sV + buf * 64 * FP + r * FP + c8, g_Vt + voff + (size_t)r * T + c8);
        }
    };

    #pragma unroll 2
    for (int id = tid; id < 1024; id += 256) {
        int r = id >> 3, c8 = (id & 7) << 3;
        cp16(sQ + r * FP + c8, g_Q + qb + (size_t)(m0 + r) * HD + c8);
    }
    stageKV(0, 0);
    CPCOMMIT;
    stageKV(1, 1);
    CPCOMMIT;

    float o[8][4];
    #pragma unroll
    for (int i = 0; i < 8; i++)
        #pragma unroll
        for (int j = 0; j < 4; j++) o[i][j] = 0.0f;
    float lsum0 = 0.0f, lsum1 = 0.0f;

    #pragma unroll 1
    for (int kt = 0; kt < 32; ++kt) {
        cpwait<1>();
        __syncthreads();

        if (kt + 2 < 32) stageKV((kt + 2) % 3, kt + 2);
        CPCOMMIT;

        const __half* K_ = sK + (kt % 3) * 64 * FP;
        const __half* V_ = sV + (kt % 3) * 64 * FP;

        float S[8][4];
        #pragma unroll
        for (int i = 0; i < 8; i++)
            #pragma unroll
            for (int j = 0; j < 4; j++) S[i][j] = 0.0f;

        #pragma unroll
        for (int ks = 0; ks < 64; ks += 16) {
            unsigned ah[4];
            ldm4(ah, sQ + ar * FP + ks + ac);
            #pragma unroll
            for (int nt2 = 0; nt2 < 4; ++nt2) {
                unsigned b4[4];
                ldm4(b4, K_ + (nt2 * 16 + brow) * FP + ks + bcol);
                mma16816(S[nt2 * 2],     ah, b4[0], b4[2]);
                mma16816(S[nt2 * 2 + 1], ah, b4[1], b4[3]);
            }
        }

        // ---- exp2 interleaved with PV ----
        #pragma unroll
        for (int j = 0; j < 4; ++j) {
            float e0 = exp2f(S[2*j  ][0]), e1 = exp2f(S[2*j  ][1]);
            float e2 = exp2f(S[2*j  ][2]), e3 = exp2f(S[2*j  ][3]);
            float e4 = exp2f(S[2*j+1][0]), e5 = exp2f(S[2*j+1][1]);
            float e6 = exp2f(S[2*j+1][2]), e7 = exp2f(S[2*j+1][3]);
            lsum0 += e0 + e1 + e4 + e5;
            lsum1 += e2 + e3 + e6 + e7;
            unsigned ph[4];
            ph[0] = pack2h(e0, e1);
            ph[1] = pack2h(e2, e3);
            ph[2] = pack2h(e4, e5);
            ph[3] = pack2h(e6, e7);
            #pragma unroll
            for (int nt2 = 0; nt2 < 4; ++nt2) {
                unsigned v4[4];
                ldm4(v4, V_ + (nt2 * 16 + brow) * FP + j * 16 + bcol);
                mma16816(o[nt2 * 2],     ph, v4[0], v4[2]);
                mma16816(o[nt2 * 2 + 1], ph, v4[1], v4[3]);
            }
        }
    }

    #pragma unroll
    for (int ofs = 1; ofs <= 2; ofs <<= 1) {
        lsum0 += __shfl_xor_sync(0xFFFFFFFFu, lsum0, ofs);
        lsum1 += __shfl_xor_sync(0xFFFFFFFFu, lsum1, ofs);
    }
    const float inv0 = 1.0f / lsum0;
    const float inv1 = 1.0f / lsum1;

    const int b = bh >> 4, h = bh & 15;
    const int gr = lane >> 2, gc2 = (lane & 3) * 2;

    #pragma unroll
    for (int nt = 0; nt < 8; ++nt) {
        #pragma unroll
        for (int hf = 0; hf < 2; ++hf) {
            float v0 = o[nt][hf * 2 + 0] * (hf ? inv1 : inv0);
            float v1 = o[nt][hf * 2 + 1] * (hf ? inv1 : inv0);
            int gm = m0 + w * 16 + gr + hf * 8;
            int gn = h * HD + nt * 8 + gc2;
            size_t off = ((size_t)(b * T + gm)) * D + gn;
            *(unsigned*)(g_C + off) = pack2h(v0, v1);
        }
    }
}

// ---------------- GEMM 4: out = ctx @ Wo^T + bo (1-term) ----------------
__global__ __launch_bounds__(256, 2) void out_mma(const float* __restrict__ bo,
                                                  float* __restrict__ out) {
    const int m0 = blockIdx.y * 128;
    const int n0 = blockIdx.x * 128;

    float cf[64];
    #pragma unroll
    for (int i = 0; i < 64; i++) cf[i] = 0.0f;

    gemm1<4, 4, 128>(cf,
        g_C + (size_t)m0 * D, D,
        g_Wh[3] + (size_t)n0 * D, D, D);

    const int w = threadIdx.x >> 5, lane = threadIdx.x & 31;
    const int warp_m = (w >> 2) * 64, warp_n = (w & 3) * 32;

    #pragma unroll
    for (int mi = 0; mi < 4; mi++)
        #pragma unroll
        for (int ni = 0; ni < 4; ni++)
            #pragma unroll
            for (int hf = 0; hf < 2; hf++) {
                float v0 = cf[(mi * 4 + ni) * 4 + hf * 2 + 0];
                float v1 = cf[(mi * 4 + ni) * 4 + hf * 2 + 1];
                int gm = m0 + warp_m + mi * 16 + (lane >> 2) + hf * 8;
                int gn = n0 + warp_n + ni * 8 + (lane & 3) * 2;
                v0 += bo[gn];
                v1 += bo[gn + 1];
                *(float2*)(out + (size_t)gm * D + gn) = make_float2(v0, v1);
            }
}

// ---------------- launch ----------------
extern "C" void kernel_launch(void* const* d_in, const int* in_sizes, int n_in,
                              void* d_out, int out_size)
{
    const float* x  = (const float*)d_in[0];
    const float* Wq = (const float*)d_in[1];
    const float* Wk = (const float*)d_in[2];
    const float* Wv = (const float*)d_in[3];
    const float* Wo = (const float*)d_in[4];
    const float* bo = (const float*)d_in[5];
    float* out = (float*)d_out;

    const int SM_G1    = 6 * 128 * GKP * 2;            // 110592 B
    const int SM_FLASH = (128 * FP + 6 * 64 * FP) * 2; // 73728 B
    cudaFuncSetAttribute(qkv_mma, cudaFuncAttributeMaxDynamicSharedMemorySize, SM_G1);
    cudaFuncSetAttribute(flash2,  cudaFuncAttributeMaxDynamicSharedMemorySize, SM_FLASH);
    cudaFuncSetAttribute(out_mma, cudaFuncAttributeMaxDynamicSharedMemorySize, SM_G1);

    conv_all<<<8192, 256>>>(x, Wq, Wk, Wv, Wo);
    qkv_mma<<<dim3(8, 32, 3), 256, SM_G1>>>();
    flash2 <<<dim3(16, 32),   256, SM_FLASH>>>();
    out_mma<<<dim3(8, 32),    256, SM_G1>>>(bo, out);
}

// round 16
// speedup vs baseline: 1.0493x; 1.0145x over previous
#include <cuda_runtime.h>
#include <cuda_fp16.h>
#include <math_constants.h>
#include <cstdint>

#define T 2048
#define D 1024
#define H 16
#define HD 64
#define BH 32
#define MTOT 4096
#define GKP 72     // gemm smem k-stride (64 elems + 8 pad)
#define FP 72      // flash smem row stride (64 elems + 8 pad)
#define TP 136     // V-transpose smem row stride (128 + 8)

// ---------------- scratch (allocation-free device globals) ----------------
__device__ __half g_xh[(size_t)MTOT * D];
__device__ __half g_Wh[4][(size_t)D * D];
__device__ __half g_Q[(size_t)BH * T * HD];                   // fp16, pre-scaled by log2e/8
__device__ __half g_K[(size_t)BH * T * HD];                   // fp16
__device__ __half g_Vt[(size_t)BH * HD * T];                  // fp16, transposed [bh][c][t]
__device__ __half g_C[(size_t)MTOT * D];                      // ctx, fp16

// ---------------- PTX helpers ----------------
__device__ __forceinline__ unsigned su32(const void* p) {
    return (unsigned)__cvta_generic_to_shared(p);
}
__device__ __forceinline__ void ldm4(unsigned* r, const void* p) {
    unsigned a = su32(p);
    asm volatile("ldmatrix.sync.aligned.m8n8.x4.shared.b16 {%0,%1,%2,%3},[%4];"
                 : "=r"(r[0]), "=r"(r[1]), "=r"(r[2]), "=r"(r[3]) : "r"(a));
}
__device__ __forceinline__ void mma16816(float* c, const unsigned* a,
                                         unsigned b0, unsigned b1) {
    asm volatile("mma.sync.aligned.m16n8k16.row.col.f32.f16.f16.f32 "
                 "{%0,%1,%2,%3},{%4,%5,%6,%7},{%8,%9},{%0,%1,%2,%3};"
                 : "+f"(c[0]), "+f"(c[1]), "+f"(c[2]), "+f"(c[3])
                 : "r"(a[0]), "r"(a[1]), "r"(a[2]), "r"(a[3]), "r"(b0), "r"(b1));
}
__device__ __forceinline__ void cp16(void* s, const void* g) {
    asm volatile("cp.async.cg.shared.global [%0],[%1],16;" :: "r"(su32(s)), "l"(g));
}
#define CPCOMMIT asm volatile("cp.async.commit_group;")
template <int N> __device__ __forceinline__ void cpwait() {
    asm volatile("cp.async.wait_group %0;" :: "n"(N));
}

__device__ __forceinline__ unsigned pack2h(float v0, float v1) {
    return ((unsigned)__half_as_ushort(__float2half_rn(v1)) << 16)
         | __half_as_ushort(__float2half_rn(v0));
}

// ---------------- 64-wide tile stage ----------------
template <int ROWS>
__device__ __forceinline__ void stage64(__half* sm, const __half* g,
                                        long ld, int k0, int tid) {
    #pragma unroll
    for (int id = tid; id < ROWS * 8; id += 256) {
        int row = id >> 3;
        int cc  = (id & 7) * 8;
        cp16(sm + row * GKP + cc, g + (size_t)row * ld + k0 + cc);
    }
}

// ---------------- fp16 1-term NT GEMM, BK=64, 3-stage, 1 barrier/iter ----------------
template <int MI, int NI, int BN>
__device__ __forceinline__ void gemm1(
    float* cf,
    const __half* __restrict__ gA, long lda,
    const __half* __restrict__ gB, long ldb,
    int K)
{
    extern __shared__ char smraw[];
    __half* sm = (__half*)smraw;
    constexpr int S   = 3;
    constexpr int ASZ = 128 * GKP;
    constexpr int BSZ = BN * GKP;
    __half* A0 = sm;
    __half* B0 = A0 + S * ASZ;

    const int tid  = threadIdx.x;
    const int w    = tid >> 5;
    const int lane = tid & 31;
    const int NWN  = BN / (NI * 8);
    const int warp_m = (w / NWN) * (MI * 16);
    const int warp_n = (w % NWN) * (NI * 8);

    const int ar = warp_m + (lane & 15);
    const int ac = (lane >> 4) << 3;
    const int brow = warp_n + (lane & 15);
    const int bcol = (lane >> 4) << 3;

    const int nit = K >> 6;

    #pragma unroll
    for (int s = 0; s < S - 1; ++s) {
        stage64<128>(A0 + s * ASZ, gA, lda, s << 6, tid);
        stage64<BN >(B0 + s * BSZ, gB, ldb, s << 6, tid);
        CPCOMMIT;
    }

    for (int it = 0; it < nit; ++it) {
        cpwait<S - 2>();
        __syncthreads();

        if (it + S - 1 < nit) {
            int nb = (it + S - 1) % S;
            int k0 = (it + S - 1) << 6;
            stage64<128>(A0 + nb * ASZ, gA, lda, k0, tid);
            stage64<BN >(B0 + nb * BSZ, gB, ldb, k0, tid);
        }
        CPCOMMIT;

        const __half* sA = A0 + (it % S) * ASZ;
        const __half* sB = B0 + (it % S) * BSZ;

        #pragma unroll
        for (int ks = 0; ks < 64; ks += 16) {
            unsigned ah[MI][4];
            #pragma unroll
            for (int mi = 0; mi < MI; mi++)
                ldm4(ah[mi], sA + (ar + mi * 16) * GKP + ks + ac);
            #pragma unroll
            for (int ni2 = 0; ni2 < NI / 2; ni2++) {
                unsigned b4[4];
                ldm4(b4, sB + (brow + ni2 * 16) * GKP + ks + bcol);
                #pragma unroll
                for (int half = 0; half < 2; half++) {
                    int ni = ni2 * 2 + half;
                    #pragma unroll
                    for (int mi = 0; mi < MI; mi++)
                        mma16816(cf + (mi * NI + ni) * 4, ah[mi], b4[half], b4[half + 2]);
                }
            }
        }
    }
    cpwait<0>();
}

// ---------------- fused conversion kernel (hi planes only) ----------------
__global__ __launch_bounds__(256) void conv_all(
    const float* __restrict__ x,  const float* __restrict__ Wq,
    const float* __restrict__ Wk, const float* __restrict__ Wv,
    const float* __restrict__ Wo)
{
    const int blk = blockIdx.x;
    const float* src;
    unsigned* dh;
    int i;
    if (blk < 4096) {
        src = x; dh = (unsigned*)g_xh;
        i = blk * 256 + threadIdx.x;
    } else {
        int wb = blk - 4096;
        int wi = wb >> 10;
        src = (wi == 0) ? Wq : (wi == 1) ? Wk : (wi == 2) ? Wv : Wo;
        dh = (unsigned*)g_Wh[wi];
        i = (wb & 1023) * 256 + threadIdx.x;
    }
    float4 v = ((const float4*)src)[i];
    dh[2 * i]     = pack2h(v.x, v.y);
    dh[2 * i + 1] = pack2h(v.z, v.w);
}

// ---------------- GEMM 1: QKV projection (1-term) ----------------
__global__ __launch_bounds__(256, 2) void qkv_mma() {
    const int z  = blockIdx.z;
    const int m0 = blockIdx.y * 128;
    const int n0 = blockIdx.x * 128;

    float cf[64];
    #pragma unroll
    for (int i = 0; i < 64; i++) cf[i] = 0.0f;

    gemm1<4, 4, 128>(cf,
        g_xh + (size_t)m0 * D, D,
        g_Wh[z] + (size_t)n0 * D, D, D);

    const int tid = threadIdx.x;
    const int w = tid >> 5, lane = tid & 31;
    const int warp_m = (w >> 2) * 64, warp_n = (w & 3) * 32;
    const float QSCALE = 0.125f * 1.4426950408889634f;

    if (z < 2) {
        #pragma unroll
        for (int mi = 0; mi < 4; mi++)
            #pragma unroll
            for (int ni = 0; ni < 4; ni++)
                #pragma unroll
                for (int hf = 0; hf < 2; hf++) {
                    float v0 = cf[(mi * 4 + ni) * 4 + hf * 2 + 0];
                    float v1 = cf[(mi * 4 + ni) * 4 + hf * 2 + 1];
                    int gm = m0 + warp_m + mi * 16 + (lane >> 2) + hf * 8;
                    int gn = n0 + warp_n + ni * 8 + (lane & 3) * 2;
                    int b = gm >> 11, t = gm & (T - 1);
                    int h = gn >> 6,  c = gn & (HD - 1);
                    size_t o = ((size_t)(b * H + h) * T + t) * HD + c;
                    if (z == 0)
                        *(unsigned*)(g_Q + o) = pack2h(v0 * QSCALE, v1 * QSCALE);
                    else
                        *(unsigned*)(g_K + o) = pack2h(v0, v1);
                }
    } else {
        extern __shared__ char smraw[];
        __half* smT = (__half*)smraw;
        __syncthreads();

        #pragma unroll
        for (int mi = 0; mi < 4; mi++)
            #pragma unroll
            for (int ni = 0; ni < 4; ni++)
                #pragma unroll
                for (int hf = 0; hf < 2; hf++) {
                    float v0 = cf[(mi * 4 + ni) * 4 + hf * 2 + 0];
                    float v1 = cf[(mi * 4 + ni) * 4 + hf * 2 + 1];
                    int ml = warp_m + mi * 16 + (lane >> 2) + hf * 8;
                    int nl = warp_n + ni * 8 + (lane & 3) * 2;
                    smT[nl * TP + ml]       = __float2half_rn(v0);
                    smT[(nl + 1) * TP + ml] = __float2half_rn(v1);
                }
        __syncthreads();

        const int b  = m0 >> 11;
        const int t0 = (m0 & (T - 1)) + (tid & 1) * 64;
        const int nl = tid >> 1;
        const int gn = n0 + nl;
        const int h  = gn >> 6, c = gn & (HD - 1);
        const uint4* srcv = (const uint4*)(smT + nl * TP + (tid & 1) * 64);
        uint4* dstv = (uint4*)(g_Vt + ((size_t)(b * H + h) * HD + c) * T + t0);
        #pragma unroll
        for (int q = 0; q < 8; ++q) dstv[q] = srcv[q];
    }
}

// ---------------- Flash attention: R13 structure + Q-fragment hoist ----------------
__global__ __launch_bounds__(256, 2) void flash2() {
    const int bh = blockIdx.y;
    const int m0 = blockIdx.x * 128;
    const size_t qb = (size_t)bh * T * HD;
    const size_t vb = (size_t)bh * HD * T;

    extern __shared__ char smraw[];
    __half* sQ = (__half*)smraw;            // 128*FP
    __half* sK = sQ + 128 * FP;             // 3 x 64*FP
    __half* sV = sK + 3 * 64 * FP;          // 3 x 64*FP

    const int tid = threadIdx.x, w = tid >> 5, lane = tid & 31;

    const int ar   = w * 16 + (lane & 15);
    const int ac   = (lane >> 4) << 3;
    const int brow = lane & 15;
    const int bcol = (lane >> 4) << 3;

    auto stageKV = [&](int buf, int kt) {
        const size_t koff = qb + (size_t)kt * 64 * HD;
        const size_t voff = vb + (size_t)kt * 64;
        #pragma unroll 2
        for (int id = tid; id < 512; id += 256) {
            int r = id >> 3, c8 = (id & 7) << 3;
            cp16(sK + buf * 64 * FP + r * FP + c8, g_K  + koff + (size_t)r * HD + c8);
            cp16(sV + buf * 64 * FP + r * FP + c8, g_Vt + voff + (size_t)r * T + c8);
        }
    };

    #pragma unroll 2
    for (int id = tid; id < 1024; id += 256) {
        int r = id >> 3, c8 = (id & 7) << 3;
        cp16(sQ + r * FP + c8, g_Q + qb + (size_t)(m0 + r) * HD + c8);
    }
    stageKV(0, 0);
    CPCOMMIT;
    stageKV(1, 1);
    CPCOMMIT;

    float o[8][4];
    #pragma unroll
    for (int i = 0; i < 8; i++)
        #pragma unroll
        for (int j = 0; j < 4; j++) o[i][j] = 0.0f;
    float lsum0 = 0.0f, lsum1 = 0.0f;

    unsigned qf[4][4];                      // hoisted Q fragments (loaded at kt==0)

    #pragma unroll 1
    for (int kt = 0; kt < 32; ++kt) {
        cpwait<1>();
        __syncthreads();

        if (kt == 0) {
            #pragma unroll
            for (int ksi = 0; ksi < 4; ++ksi)
                ldm4(qf[ksi], sQ + ar * FP + ksi * 16 + ac);
        }

        if (kt + 2 < 32) stageKV((kt + 2) % 3, kt + 2);
        CPCOMMIT;

        const __half* K_ = sK + (kt % 3) * 64 * FP;
        const __half* V_ = sV + (kt % 3) * 64 * FP;

        float S[8][4];
        #pragma unroll
        for (int i = 0; i < 8; i++)
            #pragma unroll
            for (int j = 0; j < 4; j++) S[i][j] = 0.0f;

        #pragma unroll
        for (int ksi = 0; ksi < 4; ++ksi) {
            const int ks = ksi * 16;
            #pragma unroll
            for (int nt2 = 0; nt2 < 4; ++nt2) {
                unsigned b4[4];
                ldm4(b4, K_ + (nt2 * 16 + brow) * FP + ks + bcol);
                mma16816(S[nt2 * 2],     qf[ksi], b4[0], b4[2]);
                mma16816(S[nt2 * 2 + 1], qf[ksi], b4[1], b4[3]);
            }
        }

        #pragma unroll
        for (int nt = 0; nt < 8; ++nt) {
            S[nt][0] = exp2f(S[nt][0]);
            S[nt][1] = exp2f(S[nt][1]);
            S[nt][2] = exp2f(S[nt][2]);
            S[nt][3] = exp2f(S[nt][3]);
            lsum0 += S[nt][0] + S[nt][1];
            lsum1 += S[nt][2] + S[nt][3];
        }

        #pragma unroll
        for (int j = 0; j < 4; ++j) {
            unsigned ph[4];
            ph[0] = pack2h(S[2*j  ][0], S[2*j  ][1]);
            ph[1] = pack2h(S[2*j  ][2], S[2*j  ][3]);
            ph[2] = pack2h(S[2*j+1][0], S[2*j+1][1]);
            ph[3] = pack2h(S[2*j+1][2], S[2*j+1][3]);
            #pragma unroll
            for (int nt2 = 0; nt2 < 4; ++nt2) {
                unsigned v4[4];
                ldm4(v4, V_ + (nt2 * 16 + brow) * FP + j * 16 + bcol);
                mma16816(o[nt2 * 2],     ph, v4[0], v4[2]);
                mma16816(o[nt2 * 2 + 1], ph, v4[1], v4[3]);
            }
        }
    }

    #pragma unroll
    for (int ofs = 1; ofs <= 2; ofs <<= 1) {
        lsum0 += __shfl_xor_sync(0xFFFFFFFFu, lsum0, ofs);
        lsum1 += __shfl_xor_sync(0xFFFFFFFFu, lsum1, ofs);
    }
    const float inv0 = 1.0f / lsum0;
    const float inv1 = 1.0f / lsum1;

    const int b = bh >> 4, h = bh & 15;
    const int gr = lane >> 2, gc2 = (lane & 3) * 2;

    #pragma unroll
    for (int nt = 0; nt < 8; ++nt) {
        #pragma unroll
        for (int hf = 0; hf < 2; ++hf) {
            float v0 = o[nt][hf * 2 + 0] * (hf ? inv1 : inv0);
            float v1 = o[nt][hf * 2 + 1] * (hf ? inv1 : inv0);
            int gm = m0 + w * 16 + gr + hf * 8;
            int gn = h * HD + nt * 8 + gc2;
            size_t off = ((size_t)(b * T + gm)) * D + gn;
            *(unsigned*)(g_C + off) = pack2h(v0, v1);
        }
    }
}

// ---------------- GEMM 4: out = ctx @ Wo^T + bo (1-term) ----------------
__global__ __launch_bounds__(256, 2) void out_mma(const float* __restrict__ bo,
                                                  float* __restrict__ out) {
    const int m0 = blockIdx.y * 128;
    const int n0 = blockIdx.x * 128;

    float cf[64];
    #pragma unroll
    for (int i = 0; i < 64; i++) cf[i] = 0.0f;

    gemm1<4, 4, 128>(cf,
        g_C + (size_t)m0 * D, D,
        g_Wh[3] + (size_t)n0 * D, D, D);

    const int w = threadIdx.x >> 5, lane = threadIdx.x & 31;
    const int warp_m = (w >> 2) * 64, warp_n = (w & 3) * 32;

    #pragma unroll
    for (int mi = 0; mi < 4; mi++)
        #pragma unroll
        for (int ni = 0; ni < 4; ni++)
            #pragma unroll
            for (int hf = 0; hf < 2; hf++) {
                float v0 = cf[(mi * 4 + ni) * 4 + hf * 2 + 0];
                float v1 = cf[(mi * 4 + ni) * 4 + hf * 2 + 1];
                int gm = m0 + warp_m + mi * 16 + (lane >> 2) + hf * 8;
                int gn = n0 + warp_n + ni * 8 + (lane & 3) * 2;
                v0 += bo[gn];
                v1 += bo[gn + 1];
                *(float2*)(out + (size_t)gm * D + gn) = make_float2(v0, v1);
            }
}

// ---------------- launch ----------------
extern "C" void kernel_launch(void* const* d_in, const int* in_sizes, int n_in,
                              void* d_out, int out_size)
{
    const float* x  = (const float*)d_in[0];
    const float* Wq = (const float*)d_in[1];
    const float* Wk = (const float*)d_in[2];
    const float* Wv = (const float*)d_in[3];
    const float* Wo = (const float*)d_in[4];
    const float* bo = (const float*)d_in[5];
    float* out = (float*)d_out;

    const int SM_G1    = 6 * 128 * GKP * 2;            // 110592 B
    const int SM_FLASH = (128 * FP + 6 * 64 * FP) * 2; // 73728 B
    cudaFuncSetAttribute(qkv_mma, cudaFuncAttributeMaxDynamicSharedMemorySize, SM_G1);
    cudaFuncSetAttribute(flash2,  cudaFuncAttributeMaxDynamicSharedMemorySize, SM_FLASH);
    cudaFuncSetAttribute(out_mma, cudaFuncAttributeMaxDynamicSharedMemorySize, SM_G1);

    conv_all<<<8192, 256>>>(x, Wq, Wk, Wv, Wo);
    qkv_mma<<<dim3(8, 32, 3), 256, SM_G1>>>();
    flash2 <<<dim3(16, 32),   256, SM_FLASH>>>();
    out_mma<<<dim3(8, 32),    256, SM_G1>>>(bo, out);
}